// round 6
// baseline (speedup 1.0000x reference)
#include <cuda_runtime.h>
#include <math.h>

#define B_   16
#define L_   1024
#define H_   8
#define E_   64
#define D_   512
#define LF   513
#define NROW 8192            // B_*D_
#define VPITCH 514

// ---------------- device scratch (no cudaMalloc allowed) -------------------
__device__ float  g_q2t[B_ * D_ * L_];
// transposed spectra: [bh][x][e], contiguous in e (8B-aligned rows of 64)
__device__ __align__(16) float g_qft_re[128 * LF * 64];
__device__ __align__(16) float g_qft_im[128 * LF * 64];
__device__ __align__(16) float g_kft_re[128 * LF * 64];
__device__ __align__(16) float g_kft_im[128 * LF * 64];
// v spectra: [row=bh*64+e][y], padded pitch 514 for 8B alignment
__device__ __align__(16) float g_vf_re[NROW * VPITCH];
__device__ __align__(16) float g_vf_im[NROW * VPITCH];
__device__ float  g_of_re[NROW * LF];
__device__ float  g_of_im[NROW * LF];
__device__ float2 g_tw[512];

// ---------------- packed f32x2 helpers ------------------------------------
__device__ __forceinline__ unsigned long long pk2(float lo, float hi) {
    unsigned long long r;
    asm("mov.b64 %0, {%1, %2};" : "=l"(r) : "f"(lo), "f"(hi));
    return r;
}
__device__ __forceinline__ void upk2(unsigned long long v, float& lo, float& hi) {
    asm("mov.b64 {%0, %1}, %2;" : "=f"(lo), "=f"(hi) : "l"(v));
}
__device__ __forceinline__ unsigned long long ffma2(unsigned long long a,
                                                    unsigned long long b,
                                                    unsigned long long c) {
    unsigned long long d;
    asm("fma.rn.f32x2 %0, %1, %2, %3;" : "=l"(d) : "l"(a), "l"(b), "l"(c));
    return d;
}
__device__ __forceinline__ unsigned long long neg2(unsigned long long a) {
    return a ^ 0x8000000080000000ULL;
}
__device__ __forceinline__ float sigmoidf_(float x) {
    return 1.0f / (1.0f + __expf(-x));
}
__device__ __forceinline__ int rowbase(int r) { return r * 66; }

// cp.async 8B with zero-fill (srcsize in {0,4,8})
__device__ __forceinline__ void cp8(unsigned int dst, const void* src, int srcsize) {
    asm volatile("cp.async.ca.shared.global [%0], [%1], 8, %2;"
                 :: "r"(dst), "l"(src), "r"(srcsize));
}
__device__ __forceinline__ void cp_commit() {
    asm volatile("cp.async.commit_group;");
}
template <int N>
__device__ __forceinline__ void cp_wait() {
    asm volatile("cp.async.wait_group %0;" :: "n"(N));
}

// ---------------- twiddle table: exp(+2*pi*i*j/1024) -----------------------
__global__ void twiddle_kernel() {
    int j = threadIdx.x;
    if (j < 512) {
        float s, c;
        sincosf(6.283185307179586f * (float)j * (1.0f / 1024.0f), &s, &c);
        g_tw[j] = make_float2(c, s);
    }
}

// ---------------- Conv1d(512->1024,k=3,p=1) + GLU -> g_q2t[b,c,l] ----------
// v2: l-axis packed in f32x2 pairs. Weights duplicated as (w,w) pairs in smem
// (LDS.64, oc = tx+16c -> conflict-free). x pairs shared across kw.
__global__ __launch_bounds__(256, 1) void conv_glu_kernel(
        const float* __restrict__ q, const float* __restrict__ W,
        const float* __restrict__ bias) {
    __shared__ float  sx[8 * 130];        // [8 ic][130 l] (halo 1 each side)
    __shared__ float2 swa[24 * 64];       // [24 r][64 oc] dup pairs, r=ic*3+kw
    __shared__ float2 swg[24 * 64];

    int b   = blockIdx.x >> 3;            // 16 b x 8 l-tiles
    int l0  = (blockIdx.x & 7) << 7;      // 128-wide l tile
    int oc0 = blockIdx.y << 6;            // 64-wide oc tile (of 512)
    int tid = threadIdx.x;
    int tx  = tid & 15, ty = tid >> 4;
    int lb  = ty << 3;                    // 8 l per thread (4 pairs)

    unsigned long long pa[4][4], pg[4][4];
#pragma unroll
    for (int p = 0; p < 4; p++)
#pragma unroll
        for (int c = 0; c < 4; c++) { pa[p][c] = 0ull; pg[p][c] = 0ull; }

    for (int ic0 = 0; ic0 < 512; ic0 += 8) {
        __syncthreads();
        // x tile: 8 ic x 130 l (global l in [l0-1, l0+129))
#pragma unroll
        for (int t = 0; t < 5; t++) {
            int idx = tid + (t << 8);
            if (idx < 1040) {
                int ic = idx / 130, li = idx % 130;
                int l = l0 - 1 + li;
                float v = 0.0f;
                if ((unsigned)l < 1024u)
                    v = q[((size_t)b * 1024 + l) * 512 + ic0 + ic];
                sx[ic * 130 + li] = v;
            }
        }
        // weight tiles duplicated as pairs: [r=ic*3+kw][oc]
#pragma unroll
        for (int t = 0; t < 6; t++) {
            int idx = tid + (t << 8);     // < 1536
            int oc = idx / 24, r = idx % 24;
            float wa = W[(size_t)(oc0 + oc) * 1536 + ic0 * 3 + r];
            float wg = W[(size_t)(512 + oc0 + oc) * 1536 + ic0 * 3 + r];
            swa[r * 64 + oc] = make_float2(wa, wa);
            swg[r * 64 + oc] = make_float2(wg, wg);
        }
        __syncthreads();

#pragma unroll
        for (int ic = 0; ic < 8; ic++) {
            // 11 scalars -> 10 pairs covering all (p,kw) starts s=2p+kw
            float xs[11];
#pragma unroll
            for (int s = 0; s < 11; s++) xs[s] = sx[ic * 130 + lb + s];
            unsigned long long xp[10];
#pragma unroll
            for (int s = 0; s < 10; s++) xp[s] = pk2(xs[s], xs[s + 1]);

            unsigned long long wa[4][3], wg[4][3];
#pragma unroll
            for (int c = 0; c < 4; c++)
#pragma unroll
                for (int kw = 0; kw < 3; kw++) {
                    int a = (ic * 3 + kw) * 64 + tx + (c << 4);
                    wa[c][kw] = *(const unsigned long long*)(swa + a);
                    wg[c][kw] = *(const unsigned long long*)(swg + a);
                }
#pragma unroll
            for (int p = 0; p < 4; p++)
#pragma unroll
                for (int c = 0; c < 4; c++)
#pragma unroll
                    for (int kw = 0; kw < 3; kw++) {
                        pa[p][c] = ffma2(xp[2 * p + kw], wa[c][kw], pa[p][c]);
                        pg[p][c] = ffma2(xp[2 * p + kw], wg[c][kw], pg[p][c]);
                    }
        }
    }

    // GLU epilogue, direct paired stores (8B aligned: l even)
#pragma unroll
    for (int c = 0; c < 4; c++) {
        int oc = oc0 + tx + (c << 4);
        float ba = bias[oc], bg = bias[512 + oc];
        float* po = g_q2t + ((size_t)b * 512 + oc) * 1024 + l0 + lb;
#pragma unroll
        for (int p = 0; p < 4; p++) {
            float a0, a1, g0, g1;
            upk2(pa[p][c], a0, a1);
            upk2(pg[p][c], g0, g1);
            float v0 = (a0 + ba) * sigmoidf_(g0 + bg);
            float v1 = (a1 + ba) * sigmoidf_(g1 + bg);
            *(float2*)(po + 2 * p) = make_float2(v0, v1);
        }
    }
}

// ---------------- 1024-pt radix-2 Stockham (DIF, natural order) ------------
__device__ __forceinline__ void fft1024_shared(float2* bufA, float2* bufB,
                                               float sgn, int tid) {
    float2* src = bufA;
    float2* dst = bufB;
    int m = 1;
#pragma unroll
    for (int stage = 0; stage < 10; stage++) {
#pragma unroll
        for (int u = 0; u < 2; u++) {
            int idx = tid + (u << 8);
            float2 c0 = src[idx];
            float2 c1 = src[idx + 512];
            int k = idx & (m - 1);
            int o = idx + (idx - k);
            float2 w = g_tw[idx - k];
            float wy = w.y * sgn;
            float trx = c0.x - c1.x, trY = c0.y - c1.y;
            dst[o]     = make_float2(c0.x + c1.x, c0.y + c1.y);
            dst[o + m] = make_float2(w.x * trx - wy * trY, w.x * trY + wy * trx);
        }
        __syncthreads();
        float2* t = src; src = dst; dst = t;
        m <<= 1;
    }
}

// one launch for all three rffts: blockIdx.y 0=q, 1=k, 2=v
__global__ __launch_bounds__(256) void rfft_all_kernel(const float* __restrict__ kin,
                                                       const float* __restrict__ vin) {
    __shared__ float2 bufA[1024];
    __shared__ float2 bufB[1024];
    int row = blockIdx.x, tid = threadIdx.x;
    int which = blockIdx.y;
    if (which == 0) {
        const float* p = g_q2t + (size_t)row * 1024;
        for (int i = tid; i < 1024; i += 256) bufA[i] = make_float2(p[i], 0.0f);
    } else {
        const float* in = (which == 2) ? vin : kin;
        const float* p = in + (size_t)(row >> 9) * 524288 + (row & 511);
        for (int i = tid; i < 1024; i += 256)
            bufA[i] = make_float2(p[(size_t)i * 512], 0.0f);
    }
    __syncthreads();
    fft1024_shared(bufA, bufB, -1.0f, tid);
    if (which == 2) {
        size_t ob = (size_t)row * VPITCH;
        for (int i = tid; i < 513; i += 256) {
            float2 vv = bufA[i];
            g_vf_re[ob + i] = vv.x * 0.03125f;
            g_vf_im[ob + i] = vv.y * 0.03125f;
        }
    } else {
        int bh = row >> 6, e = row & 63;
        size_t ob = (size_t)bh * LF * 64 + e;
        float* ore = which ? g_kft_re : g_qft_re;
        float* oim = which ? g_kft_im : g_qft_im;
        for (int i = tid; i < 513; i += 256) {
            float2 vv = bufA[i];
            ore[ob + (size_t)i * 64] = vv.x * 0.03125f;
            oim[ob + (size_t)i * 64] = vv.y * 0.03125f;
        }
    }
}

// ---------------- fused frequency attention: f32x2 + cp.async pipeline -----
__global__ __launch_bounds__(256) void attn_kernel() {
    extern __shared__ float sm[];
    float* Qre = sm;                  // [x][e] pitch 66
    float* Qim = sm + 4224;
    float* Kre = sm + 8448;           // [y][e] pitch 66
    float* Kim = sm + 12672;
    float* Vre = sm + 16896;          // [e][y] pitch 66
    float* Vim = sm + 21120;
    float* Tre = sm + 25344;          // [x][y] pitch 66
    float* Tim = sm + 29568;

    int bh  = blockIdx.y;
    int x0  = blockIdx.x << 6;
    int tid = threadIdx.x;
    int tx  = tid & 15, ty = tid >> 4;
    size_t tbase = (size_t)bh * LF * 64;
    size_t obase = (size_t)bh * 64 * LF;

    unsigned int sQre = (unsigned int)__cvta_generic_to_shared(Qre);
    unsigned int sQim = (unsigned int)__cvta_generic_to_shared(Qim);
    unsigned int sKre = (unsigned int)__cvta_generic_to_shared(Kre);
    unsigned int sKim = (unsigned int)__cvta_generic_to_shared(Kim);
    unsigned int sVre = (unsigned int)__cvta_generic_to_shared(Vre);
    unsigned int sVim = (unsigned int)__cvta_generic_to_shared(Vim);

    {
#pragma unroll
        for (int o = 0; o < 8; o++) {
            int flat = tid + (o << 8);
            int r = flat >> 5, p = flat & 31;
            int valid = (x0 + r) < 513;
            const float* sre = g_qft_re + tbase + (size_t)(x0 + r) * 64 + 2 * p;
            const float* sim = g_qft_im + tbase + (size_t)(x0 + r) * 64 + 2 * p;
            unsigned int d = (unsigned int)((r * 66 + 2 * p) * 4);
            cp8(sQre + d, valid ? sre : g_qft_re, valid ? 8 : 0);
            cp8(sQim + d, valid ? sim : g_qft_im, valid ? 8 : 0);
        }
#pragma unroll
        for (int o = 0; o < 8; o++) {
            int flat = tid + (o << 8);
            int r = flat >> 5, p = flat & 31;
            const float* sre = g_kft_re + tbase + (size_t)r * 64 + 2 * p;
            const float* sim = g_kft_im + tbase + (size_t)r * 64 + 2 * p;
            unsigned int d = (unsigned int)((r * 66 + 2 * p) * 4);
            cp8(sKre + d, sre, 8);
            cp8(sKim + d, sim, 8);
        }
        cp_commit();
#pragma unroll
        for (int o = 0; o < 8; o++) {
            int flat = tid + (o << 8);
            int r = flat >> 5, p = flat & 31;
            const float* sre = g_vf_re + (size_t)(bh * 64 + r) * VPITCH + 2 * p;
            const float* sim = g_vf_im + (size_t)(bh * 64 + r) * VPITCH + 2 * p;
            unsigned int d = (unsigned int)((r * 66 + 2 * p) * 4);
            cp8(sVre + d, sre, 8);
            cp8(sVim + d, sim, 8);
        }
        cp_commit();
    }

    int qb[4], kb[4];
#pragma unroll
    for (int i = 0; i < 4; i++) qb[i] = rowbase((ty << 2) + i);
#pragma unroll
    for (int j = 0; j < 4; j++) kb[j] = rowbase(tx + (j << 4));

    unsigned long long ore_p[4][4], oim_p[4][4];
#pragma unroll
    for (int i = 0; i < 4; i++)
#pragma unroll
        for (int j = 0; j < 4; j++) { ore_p[i][j] = 0ull; oim_p[i][j] = 0ull; }
    float Dacc[4] = {};

    cp_wait<1>();
    __syncthreads();

    for (int yt = 0; yt < 9; yt++) {
        unsigned long long sre_p[4][4], sim_p[4][4];
#pragma unroll
        for (int i = 0; i < 4; i++)
#pragma unroll
            for (int j = 0; j < 4; j++) { sre_p[i][j] = 0ull; sim_p[i][j] = 0ull; }

        for (int e2 = 0; e2 < 32; e2++) {
            unsigned long long qr[4], qi[4], qrn[4], kr[4], ki[4];
            int off = e2 << 1;
#pragma unroll
            for (int i = 0; i < 4; i++) {
                qr[i] = *(const unsigned long long*)(Qre + qb[i] + off);
                qi[i] = *(const unsigned long long*)(Qim + qb[i] + off);
                qrn[i] = neg2(qr[i]);
            }
#pragma unroll
            for (int j = 0; j < 4; j++) {
                kr[j] = *(const unsigned long long*)(Kre + kb[j] + off);
                ki[j] = *(const unsigned long long*)(Kim + kb[j] + off);
            }
#pragma unroll
            for (int i = 0; i < 4; i++)
#pragma unroll
                for (int j = 0; j < 4; j++) {
                    sre_p[i][j] = ffma2(qr[i],  kr[j], sre_p[i][j]);
                    sre_p[i][j] = ffma2(qi[i],  ki[j], sre_p[i][j]);
                    sim_p[i][j] = ffma2(qi[i],  kr[j], sim_p[i][j]);
                    sim_p[i][j] = ffma2(qrn[i], ki[j], sim_p[i][j]);
                }
        }
        __syncthreads();

        if (yt < 8) {
            int y0n = (yt + 1) << 6;
#pragma unroll
            for (int o = 0; o < 8; o++) {
                int flat = tid + (o << 8);
                int r = flat >> 5, p = flat & 31;
                int valid = (y0n + r) < 513;
                const float* sre = g_kft_re + tbase + (size_t)(y0n + r) * 64 + 2 * p;
                const float* sim = g_kft_im + tbase + (size_t)(y0n + r) * 64 + 2 * p;
                unsigned int d = (unsigned int)((r * 66 + 2 * p) * 4);
                cp8(sKre + d, valid ? sre : g_kft_re, valid ? 8 : 0);
                cp8(sKim + d, valid ? sim : g_kft_im, valid ? 8 : 0);
            }
            cp_commit();
        }

#pragma unroll
        for (int i = 0; i < 4; i++)
#pragma unroll
            for (int j = 0; j < 4; j++) {
                float a0, a1, b0, b1;
                upk2(sre_p[i][j], a0, a1);
                upk2(sim_p[i][j], b0, b1);
                float sr = (a0 + a1) * 0.125f;
                float si = (b0 + b1) * 0.125f;
                float mg = sqrtf(sr * sr + si * si);
                float w  = 1.0f + sigmoidf_(mg);
                Dacc[i] += mg * w;
                int a = qb[i] + tx + (j << 4);
                Tre[a] = sr * w;
                Tim[a] = si * w;
            }

        if (yt < 8) cp_wait<1>(); else cp_wait<0>();
        __syncthreads();

        for (int y2 = 0; y2 < 32; y2++) {
            unsigned long long tr[4], ti[4], tin[4], vr[4], vi[4];
            int off = y2 << 1;
#pragma unroll
            for (int i = 0; i < 4; i++) {
                tr[i] = *(const unsigned long long*)(Tre + qb[i] + off);
                ti[i] = *(const unsigned long long*)(Tim + qb[i] + off);
                tin[i] = neg2(ti[i]);
            }
#pragma unroll
            for (int j = 0; j < 4; j++) {
                vr[j] = *(const unsigned long long*)(Vre + kb[j] + off);
                vi[j] = *(const unsigned long long*)(Vim + kb[j] + off);
            }
#pragma unroll
            for (int i = 0; i < 4; i++)
#pragma unroll
                for (int j = 0; j < 4; j++) {
                    ore_p[i][j] = ffma2(tr[i],  vr[j], ore_p[i][j]);
                    ore_p[i][j] = ffma2(tin[i], vi[j], ore_p[i][j]);
                    oim_p[i][j] = ffma2(tr[i],  vi[j], oim_p[i][j]);
                    oim_p[i][j] = ffma2(ti[i],  vr[j], oim_p[i][j]);
                }
        }
        __syncthreads();

        if (yt < 8) {
            int y0n = (yt + 1) << 6;
#pragma unroll
            for (int o = 0; o < 8; o++) {
                int flat = tid + (o << 8);
                int r = flat >> 5, p = flat & 31;
                int rem = 513 - (y0n + 2 * p);
                int sz = rem >= 2 ? 8 : (rem == 1 ? 4 : 0);
                const float* sre = g_vf_re + (size_t)(bh * 64 + r) * VPITCH + y0n + 2 * p;
                const float* sim = g_vf_im + (size_t)(bh * 64 + r) * VPITCH + y0n + 2 * p;
                unsigned int d = (unsigned int)((r * 66 + 2 * p) * 4);
                cp8(sVre + d, sre, sz);
                cp8(sVim + d, sim, sz);
            }
            cp_commit();
            cp_wait<1>();
            __syncthreads();
        }
    }

#pragma unroll
    for (int i = 0; i < 4; i++) {
        float dsum = Dacc[i];
        dsum += __shfl_xor_sync(0xffffffffu, dsum, 1);
        dsum += __shfl_xor_sync(0xffffffffu, dsum, 2);
        dsum += __shfl_xor_sync(0xffffffffu, dsum, 4);
        dsum += __shfl_xor_sync(0xffffffffu, dsum, 8);
        Dacc[i] = 1.0f / fmaxf(dsum, 1e-12f);
    }
#pragma unroll
    for (int i = 0; i < 4; i++) {
        int x = x0 + (ty << 2) + i;
        if (x < 513) {
#pragma unroll
            for (int j = 0; j < 4; j++) {
                int e = tx + (j << 4);
                float a0, a1, b0, b1;
                upk2(ore_p[i][j], a0, a1);
                upk2(oim_p[i][j], b0, b1);
                g_of_re[obase + (size_t)e * 513 + x] = (a0 + a1) * Dacc[i];
                g_of_im[obase + (size_t)e * 513 + x] = (b0 + b1) * Dacc[i];
            }
        }
    }
}

// ---------------- irfft (ortho) + scatter to out[b,l,h,e] ------------------
__global__ __launch_bounds__(256) void irfft_kernel(float* __restrict__ out) {
    __shared__ float2 bufA[1024];
    __shared__ float2 bufB[1024];
    int row = blockIdx.x, tid = threadIdx.x;
    const float* pr = g_of_re + (size_t)row * 513;
    const float* pi = g_of_im + (size_t)row * 513;
    for (int i = tid; i < 1024; i += 256) {
        float re, im;
        if (i < 513) { re = pr[i];        im =  pi[i]; }
        else         { re = pr[1024 - i]; im = -pi[1024 - i]; }
        bufA[i] = make_float2(re, im);
    }
    __syncthreads();
    fft1024_shared(bufA, bufB, 1.0f, tid);
    int b = row >> 9, c = row & 511;
    float* po = out + (size_t)b * 524288 + c;
    for (int i = tid; i < 1024; i += 256)
        po[(size_t)i * 512] = bufA[i].x * 0.03125f;
}

// ---------------- launch ---------------------------------------------------
extern "C" void kernel_launch(void* const* d_in, const int* in_sizes, int n_in,
                              void* d_out, int out_size) {
    const float* q    = (const float*)d_in[0];
    const float* k    = (const float*)d_in[1];
    const float* v    = (const float*)d_in[2];
    const float* W    = (const float*)d_in[3];
    const float* bias = (const float*)d_in[4];
    float* out = (float*)d_out;

    const int attn_smem = 33792 * (int)sizeof(float);   // 135168 B
    cudaFuncSetAttribute(attn_kernel,
                         cudaFuncAttributeMaxDynamicSharedMemorySize, attn_smem);

    twiddle_kernel<<<1, 512>>>();
    conv_glu_kernel<<<dim3(128, 8), 256>>>(q, W, bias);
    rfft_all_kernel<<<dim3(NROW, 3), 256>>>(k, v);
    attn_kernel<<<dim3(9, 128), 256, attn_smem>>>();
    irfft_kernel<<<NROW, 256>>>(out);
}

// round 8
// speedup vs baseline: 1.5087x; 1.5087x over previous
#include <cuda_runtime.h>
#include <math.h>

#define B_   16
#define L_   1024
#define H_   8
#define E_   64
#define D_   512
#define LF   513
#define NROW 8192            // B_*D_
#define VPITCH 514

// ---------------- device scratch (no cudaMalloc allowed) -------------------
__device__ float  g_q2t[B_ * D_ * L_];
__device__ __align__(16) float g_Wt[2 * 1536 * 512];   // [half][r][oc]
// transposed spectra: [bh][x][e], contiguous in e
__device__ __align__(16) float g_qft_re[128 * LF * 64];
__device__ __align__(16) float g_qft_im[128 * LF * 64];
__device__ __align__(16) float g_kft_re[128 * LF * 64];
__device__ __align__(16) float g_kft_im[128 * LF * 64];
// v spectra: [row=bh*64+e][y], padded pitch 514
__device__ __align__(16) float g_vf_re[NROW * VPITCH];
__device__ __align__(16) float g_vf_im[NROW * VPITCH];
__device__ float  g_of_re[NROW * LF];
__device__ float  g_of_im[NROW * LF];
__device__ float2 g_tw[512];

// ---------------- packed f32x2 helpers ------------------------------------
__device__ __forceinline__ unsigned long long pk2(float lo, float hi) {
    unsigned long long r;
    asm("mov.b64 %0, {%1, %2};" : "=l"(r) : "f"(lo), "f"(hi));
    return r;
}
__device__ __forceinline__ void upk2(unsigned long long v, float& lo, float& hi) {
    asm("mov.b64 {%0, %1}, %2;" : "=f"(lo), "=f"(hi) : "l"(v));
}
__device__ __forceinline__ unsigned long long ffma2(unsigned long long a,
                                                    unsigned long long b,
                                                    unsigned long long c) {
    unsigned long long d;
    asm("fma.rn.f32x2 %0, %1, %2, %3;" : "=l"(d) : "l"(a), "l"(b), "l"(c));
    return d;
}
__device__ __forceinline__ unsigned long long neg2(unsigned long long a) {
    return a ^ 0x8000000080000000ULL;
}
__device__ __forceinline__ float sigmoidf_(float x) {
    return 1.0f / (1.0f + __expf(-x));
}
__device__ __forceinline__ int rowbase(int r) { return r * 66; }

// cp.async helpers
__device__ __forceinline__ void cp8(unsigned int dst, const void* src, int srcsize) {
    asm volatile("cp.async.ca.shared.global [%0], [%1], 8, %2;"
                 :: "r"(dst), "l"(src), "r"(srcsize));
}
__device__ __forceinline__ void cp16(unsigned int dst, const void* src, int srcsize) {
    asm volatile("cp.async.cg.shared.global [%0], [%1], 16, %2;"
                 :: "r"(dst), "l"(src), "r"(srcsize));
}
__device__ __forceinline__ void cp_commit() {
    asm volatile("cp.async.commit_group;");
}
template <int N>
__device__ __forceinline__ void cp_wait() {
    asm volatile("cp.async.wait_group %0;" :: "n"(N));
}

// ---------------- init: transpose W + twiddle table ------------------------
__global__ __launch_bounds__(256) void init_kernel(const float* __restrict__ W) {
    int idx = blockIdx.x * 256 + threadIdx.x;
    if (idx < 2 * 1536 * 512) {
        int r = idx % 1536, oc = idx / 1536;        // read contiguous in r
        int half = oc >> 9, o = oc & 511;
        g_Wt[((size_t)half * 1536 + r) * 512 + o] = W[idx];
    }
    if (blockIdx.x == 0) {
        for (int j = threadIdx.x; j < 512; j += 256) {
            float s, c;
            sincosf(6.283185307179586f * (float)j * (1.0f / 1024.0f), &s, &c);
            g_tw[j] = make_float2(c, s);
        }
    }
}

// ---------------- Conv1d(512->1024,k=3,p=1)+GLU, cp.async double-buffered --
// Block: 64 l x 64 oc (both GLU halves). Chunk = 16 ic.
// smem: sx[2][66*16] (x as [l][ic]), sw[2][2*48*64] ([half][r][oc]).
__global__ __launch_bounds__(256, 2) void conv_glu_kernel(
        const float* __restrict__ q, const float* __restrict__ bias) {
    extern __shared__ float csm[];
    float* sx = csm;              // 2 * 1056
    float* sw = csm + 2112;       // 2 * 6144

    int b   = blockIdx.x >> 4;
    int l0  = (blockIdx.x & 15) << 6;
    int oc0 = blockIdx.y << 6;
    int tid = threadIdx.x;
    int tx  = tid & 15, ty = tid >> 4;
    int lb  = ty << 2;            // 4 l per thread

    unsigned int sxa = (unsigned int)__cvta_generic_to_shared(sx);
    unsigned int swa = (unsigned int)__cvta_generic_to_shared(sw);

    auto issue = [&](int chunk, int buf) {
        int ic0 = chunk << 4;
        // x tile: 66 l-rows x 16 ic (16B segs), zero-fill halo
        for (int t = tid; t < 264; t += 256) {
            int li = t >> 2, seg = t & 3;
            int l = l0 - 1 + li;
            int valid = (unsigned)l < 1024u;
            const float* src = q + ((size_t)b * 1024 + (valid ? l : 0)) * 512
                               + ic0 + (seg << 2);
            cp16(sxa + (unsigned)((buf * 1056 + li * 16 + (seg << 2)) * 4),
                 src, valid ? 16 : 0);
        }
        // W tiles: [half][48 r][64 oc], contiguous in oc
#pragma unroll
        for (int o = 0; o < 6; o++) {
            int t = tid + (o << 8);
            int half = t >= 768;
            int tt = t - (half ? 768 : 0);          // FIX: 767 is not 2^k-1
            int r = tt >> 4, seg = tt & 15;
            const float* src = g_Wt + ((size_t)half * 1536 + ic0 * 3 + r) * 512
                               + oc0 + (seg << 2);
            cp16(swa + (unsigned)((buf * 6144 + half * 3072 + r * 64 + (seg << 2)) * 4),
                 src, 16);
        }
        cp_commit();
    };

    issue(0, 0);

    unsigned long long pa[4][2], pg[4][2];
#pragma unroll
    for (int i = 0; i < 4; i++)
#pragma unroll
        for (int c = 0; c < 2; c++) { pa[i][c] = 0ull; pg[i][c] = 0ull; }

    for (int ch = 0; ch < 32; ch++) {
        int buf = ch & 1;
        if (ch < 31) {
            issue(ch + 1, buf ^ 1);   // buf^1 free: compute(ch-1) synced
            cp_wait<1>();
        } else {
            cp_wait<0>();
        }
        __syncthreads();

        const float* xb = sx + buf * 1056;
        const float* wb = sw + buf * 6144;
#pragma unroll
        for (int ic = 0; ic < 16; ic++) {
            float xs[6];
#pragma unroll
            for (int s = 0; s < 6; s++) xs[s] = xb[(lb + s) * 16 + ic];
            unsigned long long xd[6];
#pragma unroll
            for (int s = 0; s < 6; s++) xd[s] = pk2(xs[s], xs[s]);
            unsigned long long wva[2][3], wvg[2][3];
#pragma unroll
            for (int c = 0; c < 2; c++)
#pragma unroll
                for (int kw = 0; kw < 3; kw++) {
                    int a = (ic * 3 + kw) * 64 + ((tx + (c << 4)) << 1);
                    wva[c][kw] = *(const unsigned long long*)(wb + a);
                    wvg[c][kw] = *(const unsigned long long*)(wb + 3072 + a);
                }
#pragma unroll
            for (int i = 0; i < 4; i++)
#pragma unroll
                for (int c = 0; c < 2; c++)
#pragma unroll
                    for (int kw = 0; kw < 3; kw++) {
                        pa[i][c] = ffma2(xd[i + kw], wva[c][kw], pa[i][c]);
                        pg[i][c] = ffma2(xd[i + kw], wvg[c][kw], pg[i][c]);
                    }
        }
        __syncthreads();   // buf free for next issue
    }

    // GLU epilogue: stage [64 oc][65 l] in smem, coalesced store along l
    float* st = csm;
#pragma unroll
    for (int c = 0; c < 2; c++) {
        int p = tx + (c << 4);
        float b0a = bias[oc0 + 2 * p],       b1a = bias[oc0 + 2 * p + 1];
        float b0g = bias[512 + oc0 + 2 * p], b1g = bias[512 + oc0 + 2 * p + 1];
#pragma unroll
        for (int i = 0; i < 4; i++) {
            float a0, a1, g0, g1;
            upk2(pa[i][c], a0, a1);
            upk2(pg[i][c], g0, g1);
            st[(2 * p) * 65 + lb + i]     = (a0 + b0a) * sigmoidf_(g0 + b0g);
            st[(2 * p + 1) * 65 + lb + i] = (a1 + b1a) * sigmoidf_(g1 + b1g);
        }
    }
    __syncthreads();
#pragma unroll
    for (int t = 0; t < 16; t++) {
        int idx = tid + (t << 8);
        int c2 = idx >> 6, li = idx & 63;
        g_q2t[((size_t)b * 512 + oc0 + c2) * 1024 + l0 + li] = st[c2 * 65 + li];
    }
}

// ---------------- 1024-pt radix-2 Stockham (DIF, natural order) ------------
__device__ __forceinline__ void fft1024_shared(float2* bufA, float2* bufB,
                                               float sgn, int tid) {
    float2* src = bufA;
    float2* dst = bufB;
    int m = 1;
#pragma unroll
    for (int stage = 0; stage < 10; stage++) {
#pragma unroll
        for (int u = 0; u < 2; u++) {
            int idx = tid + (u << 8);
            float2 c0 = src[idx];
            float2 c1 = src[idx + 512];
            int k = idx & (m - 1);
            int o = idx + (idx - k);
            float2 w = g_tw[idx - k];
            float wy = w.y * sgn;
            float trx = c0.x - c1.x, trY = c0.y - c1.y;
            dst[o]     = make_float2(c0.x + c1.x, c0.y + c1.y);
            dst[o + m] = make_float2(w.x * trx - wy * trY, w.x * trY + wy * trx);
        }
        __syncthreads();
        float2* t = src; src = dst; dst = t;
        m <<= 1;
    }
}

// which: 0 = q (g_q2t), 1 = k -> transposed, 2 = v -> padded rows
__global__ __launch_bounds__(256) void rfft_one_kernel(const float* __restrict__ in,
                                                       int which) {
    __shared__ float2 bufA[1024];
    __shared__ float2 bufB[1024];
    int row = blockIdx.x, tid = threadIdx.x;
    if (which == 0) {
        const float* p = g_q2t + (size_t)row * 1024;
        for (int i = tid; i < 1024; i += 256) bufA[i] = make_float2(p[i], 0.0f);
    } else {
        const float* p = in + (size_t)(row >> 9) * 524288 + (row & 511);
        for (int i = tid; i < 1024; i += 256)
            bufA[i] = make_float2(p[(size_t)i * 512], 0.0f);
    }
    __syncthreads();
    fft1024_shared(bufA, bufB, -1.0f, tid);
    if (which == 2) {
        size_t ob = (size_t)row * VPITCH;
        for (int i = tid; i < 513; i += 256) {
            float2 vv = bufA[i];
            g_vf_re[ob + i] = vv.x * 0.03125f;
            g_vf_im[ob + i] = vv.y * 0.03125f;
        }
    } else {
        int bh = row >> 6, e = row & 63;
        size_t ob = (size_t)bh * LF * 64 + e;
        float* ore = which ? g_kft_re : g_qft_re;
        float* oim = which ? g_kft_im : g_qft_im;
        for (int i = tid; i < 513; i += 256) {
            float2 vv = bufA[i];
            ore[ob + (size_t)i * 64] = vv.x * 0.03125f;
            oim[ob + (size_t)i * 64] = vv.y * 0.03125f;
        }
    }
}

// ---------------- fused frequency attention: f32x2 + cp.async pipeline -----
__global__ __launch_bounds__(256) void attn_kernel() {
    extern __shared__ float sm[];
    float* Qre = sm;                  // [x][e] pitch 66
    float* Qim = sm + 4224;
    float* Kre = sm + 8448;           // [y][e] pitch 66
    float* Kim = sm + 12672;
    float* Vre = sm + 16896;          // [e][y] pitch 66
    float* Vim = sm + 21120;
    float* Tre = sm + 25344;          // [x][y] pitch 66
    float* Tim = sm + 29568;

    int bh  = blockIdx.y;
    int x0  = blockIdx.x << 6;
    int tid = threadIdx.x;
    int tx  = tid & 15, ty = tid >> 4;
    size_t tbase = (size_t)bh * LF * 64;
    size_t obase = (size_t)bh * 64 * LF;

    unsigned int sQre = (unsigned int)__cvta_generic_to_shared(Qre);
    unsigned int sQim = (unsigned int)__cvta_generic_to_shared(Qim);
    unsigned int sKre = (unsigned int)__cvta_generic_to_shared(Kre);
    unsigned int sKim = (unsigned int)__cvta_generic_to_shared(Kim);
    unsigned int sVre = (unsigned int)__cvta_generic_to_shared(Vre);
    unsigned int sVim = (unsigned int)__cvta_generic_to_shared(Vim);

    {
#pragma unroll
        for (int o = 0; o < 8; o++) {
            int flat = tid + (o << 8);
            int r = flat >> 5, p = flat & 31;
            int valid = (x0 + r) < 513;
            const float* sre = g_qft_re + tbase + (size_t)(x0 + r) * 64 + 2 * p;
            const float* sim = g_qft_im + tbase + (size_t)(x0 + r) * 64 + 2 * p;
            unsigned int d = (unsigned int)((r * 66 + 2 * p) * 4);
            cp8(sQre + d, valid ? sre : g_qft_re, valid ? 8 : 0);
            cp8(sQim + d, valid ? sim : g_qft_im, valid ? 8 : 0);
        }
#pragma unroll
        for (int o = 0; o < 8; o++) {
            int flat = tid + (o << 8);
            int r = flat >> 5, p = flat & 31;
            const float* sre = g_kft_re + tbase + (size_t)r * 64 + 2 * p;
            const float* sim = g_kft_im + tbase + (size_t)r * 64 + 2 * p;
            unsigned int d = (unsigned int)((r * 66 + 2 * p) * 4);
            cp8(sKre + d, sre, 8);
            cp8(sKim + d, sim, 8);
        }
        cp_commit();
#pragma unroll
        for (int o = 0; o < 8; o++) {
            int flat = tid + (o << 8);
            int r = flat >> 5, p = flat & 31;
            const float* sre = g_vf_re + (size_t)(bh * 64 + r) * VPITCH + 2 * p;
            const float* sim = g_vf_im + (size_t)(bh * 64 + r) * VPITCH + 2 * p;
            unsigned int d = (unsigned int)((r * 66 + 2 * p) * 4);
            cp8(sVre + d, sre, 8);
            cp8(sVim + d, sim, 8);
        }
        cp_commit();
    }

    int qb[4], kb[4];
#pragma unroll
    for (int i = 0; i < 4; i++) qb[i] = rowbase((ty << 2) + i);
#pragma unroll
    for (int j = 0; j < 4; j++) kb[j] = rowbase(tx + (j << 4));

    unsigned long long ore_p[4][4], oim_p[4][4];
#pragma unroll
    for (int i = 0; i < 4; i++)
#pragma unroll
        for (int j = 0; j < 4; j++) { ore_p[i][j] = 0ull; oim_p[i][j] = 0ull; }
    float Dacc[4] = {};

    cp_wait<1>();
    __syncthreads();

    for (int yt = 0; yt < 9; yt++) {
        unsigned long long sre_p[4][4], sim_p[4][4];
#pragma unroll
        for (int i = 0; i < 4; i++)
#pragma unroll
            for (int j = 0; j < 4; j++) { sre_p[i][j] = 0ull; sim_p[i][j] = 0ull; }

        for (int e2 = 0; e2 < 32; e2++) {
            unsigned long long qr[4], qi[4], qrn[4], kr[4], ki[4];
            int off = e2 << 1;
#pragma unroll
            for (int i = 0; i < 4; i++) {
                qr[i] = *(const unsigned long long*)(Qre + qb[i] + off);
                qi[i] = *(const unsigned long long*)(Qim + qb[i] + off);
                qrn[i] = neg2(qr[i]);
            }
#pragma unroll
            for (int j = 0; j < 4; j++) {
                kr[j] = *(const unsigned long long*)(Kre + kb[j] + off);
                ki[j] = *(const unsigned long long*)(Kim + kb[j] + off);
            }
#pragma unroll
            for (int i = 0; i < 4; i++)
#pragma unroll
                for (int j = 0; j < 4; j++) {
                    sre_p[i][j] = ffma2(qr[i],  kr[j], sre_p[i][j]);
                    sre_p[i][j] = ffma2(qi[i],  ki[j], sre_p[i][j]);
                    sim_p[i][j] = ffma2(qi[i],  kr[j], sim_p[i][j]);
                    sim_p[i][j] = ffma2(qrn[i], ki[j], sim_p[i][j]);
                }
        }
        __syncthreads();

        if (yt < 8) {
            int y0n = (yt + 1) << 6;
#pragma unroll
            for (int o = 0; o < 8; o++) {
                int flat = tid + (o << 8);
                int r = flat >> 5, p = flat & 31;
                int valid = (y0n + r) < 513;
                const float* sre = g_kft_re + tbase + (size_t)(y0n + r) * 64 + 2 * p;
                const float* sim = g_kft_im + tbase + (size_t)(y0n + r) * 64 + 2 * p;
                unsigned int d = (unsigned int)((r * 66 + 2 * p) * 4);
                cp8(sKre + d, valid ? sre : g_kft_re, valid ? 8 : 0);
                cp8(sKim + d, valid ? sim : g_kft_im, valid ? 8 : 0);
            }
            cp_commit();
        }

#pragma unroll
        for (int i = 0; i < 4; i++)
#pragma unroll
            for (int j = 0; j < 4; j++) {
                float a0, a1, b0, b1;
                upk2(sre_p[i][j], a0, a1);
                upk2(sim_p[i][j], b0, b1);
                float sr = (a0 + a1) * 0.125f;
                float si = (b0 + b1) * 0.125f;
                float mg = sqrtf(sr * sr + si * si);
                float w  = 1.0f + sigmoidf_(mg);
                Dacc[i] += mg * w;
                int a = qb[i] + tx + (j << 4);
                Tre[a] = sr * w;
                Tim[a] = si * w;
            }

        if (yt < 8) cp_wait<1>(); else cp_wait<0>();
        __syncthreads();

        for (int y2 = 0; y2 < 32; y2++) {
            unsigned long long tr[4], ti[4], tin[4], vr[4], vi[4];
            int off = y2 << 1;
#pragma unroll
            for (int i = 0; i < 4; i++) {
                tr[i] = *(const unsigned long long*)(Tre + qb[i] + off);
                ti[i] = *(const unsigned long long*)(Tim + qb[i] + off);
                tin[i] = neg2(ti[i]);
            }
#pragma unroll
            for (int j = 0; j < 4; j++) {
                vr[j] = *(const unsigned long long*)(Vre + kb[j] + off);
                vi[j] = *(const unsigned long long*)(Vim + kb[j] + off);
            }
#pragma unroll
            for (int i = 0; i < 4; i++)
#pragma unroll
                for (int j = 0; j < 4; j++) {
                    ore_p[i][j] = ffma2(tr[i],  vr[j], ore_p[i][j]);
                    ore_p[i][j] = ffma2(tin[i], vi[j], ore_p[i][j]);
                    oim_p[i][j] = ffma2(tr[i],  vi[j], oim_p[i][j]);
                    oim_p[i][j] = ffma2(ti[i],  vr[j], oim_p[i][j]);
                }
        }
        __syncthreads();

        if (yt < 8) {
            int y0n = (yt + 1) << 6;
#pragma unroll
            for (int o = 0; o < 8; o++) {
                int flat = tid + (o << 8);
                int r = flat >> 5, p = flat & 31;
                int rem = 513 - (y0n + 2 * p);
                int sz = rem >= 2 ? 8 : (rem == 1 ? 4 : 0);
                const float* sre = g_vf_re + (size_t)(bh * 64 + r) * VPITCH + y0n + 2 * p;
                const float* sim = g_vf_im + (size_t)(bh * 64 + r) * VPITCH + y0n + 2 * p;
                unsigned int d = (unsigned int)((r * 66 + 2 * p) * 4);
                cp8(sVre + d, sre, sz);
                cp8(sVim + d, sim, sz);
            }
            cp_commit();
            cp_wait<1>();
            __syncthreads();
        }
    }

#pragma unroll
    for (int i = 0; i < 4; i++) {
        float dsum = Dacc[i];
        dsum += __shfl_xor_sync(0xffffffffu, dsum, 1);
        dsum += __shfl_xor_sync(0xffffffffu, dsum, 2);
        dsum += __shfl_xor_sync(0xffffffffu, dsum, 4);
        dsum += __shfl_xor_sync(0xffffffffu, dsum, 8);
        Dacc[i] = 1.0f / fmaxf(dsum, 1e-12f);
    }
#pragma unroll
    for (int i = 0; i < 4; i++) {
        int x = x0 + (ty << 2) + i;
        if (x < 513) {
#pragma unroll
            for (int j = 0; j < 4; j++) {
                int e = tx + (j << 4);
                float a0, a1, b0, b1;
                upk2(ore_p[i][j], a0, a1);
                upk2(oim_p[i][j], b0, b1);
                g_of_re[obase + (size_t)e * 513 + x] = (a0 + a1) * Dacc[i];
                g_of_im[obase + (size_t)e * 513 + x] = (b0 + b1) * Dacc[i];
            }
        }
    }
}

// ---------------- irfft (ortho) + scatter to out[b,l,h,e] ------------------
__global__ __launch_bounds__(256) void irfft_kernel(float* __restrict__ out) {
    __shared__ float2 bufA[1024];
    __shared__ float2 bufB[1024];
    int row = blockIdx.x, tid = threadIdx.x;
    const float* pr = g_of_re + (size_t)row * 513;
    const float* pi = g_of_im + (size_t)row * 513;
    for (int i = tid; i < 1024; i += 256) {
        float re, im;
        if (i < 513) { re = pr[i];        im =  pi[i]; }
        else         { re = pr[1024 - i]; im = -pi[1024 - i]; }
        bufA[i] = make_float2(re, im);
    }
    __syncthreads();
    fft1024_shared(bufA, bufB, 1.0f, tid);
    int b = row >> 9, c = row & 511;
    float* po = out + (size_t)b * 524288 + c;
    for (int i = tid; i < 1024; i += 256)
        po[(size_t)i * 512] = bufA[i].x * 0.03125f;
}

// ---------------- launch ---------------------------------------------------
extern "C" void kernel_launch(void* const* d_in, const int* in_sizes, int n_in,
                              void* d_out, int out_size) {
    const float* q    = (const float*)d_in[0];
    const float* k    = (const float*)d_in[1];
    const float* v    = (const float*)d_in[2];
    const float* W    = (const float*)d_in[3];
    const float* bias = (const float*)d_in[4];
    float* out = (float*)d_out;

    const int attn_smem = 33792 * (int)sizeof(float);   // 135168 B
    cudaFuncSetAttribute(attn_kernel,
                         cudaFuncAttributeMaxDynamicSharedMemorySize, attn_smem);
    const int conv_smem = (2112 + 12288) * (int)sizeof(float);  // 57600 B
    cudaFuncSetAttribute(conv_glu_kernel,
                         cudaFuncAttributeMaxDynamicSharedMemorySize, conv_smem);

    init_kernel<<<6144, 256>>>(W);
    rfft_one_kernel<<<NROW, 256>>>(k, 1);
    rfft_one_kernel<<<NROW, 256>>>(v, 2);
    conv_glu_kernel<<<dim3(256, 8), 256, conv_smem>>>(q, bias);   // ncu slot
    rfft_one_kernel<<<NROW, 256>>>(nullptr, 0);
    attn_kernel<<<dim3(9, 128), 256, attn_smem>>>();
    irfft_kernel<<<NROW, 256>>>(out);
}

// round 9
// speedup vs baseline: 1.5554x; 1.0310x over previous
#include <cuda_runtime.h>
#include <math.h>

#define B_   16
#define L_   1024
#define H_   8
#define E_   64
#define D_   512
#define LF   513
#define NROW 8192            // B_*D_
#define VPITCH 514

// ---------------- device scratch (no cudaMalloc allowed) -------------------
__device__ float  g_q2t[B_ * D_ * L_];
__device__ __align__(16) float g_Wt[2 * 1536 * 512];   // [half][r][oc]
// transposed spectra: [bh][x][e], contiguous in e
__device__ __align__(16) float g_qft_re[128 * LF * 64];
__device__ __align__(16) float g_qft_im[128 * LF * 64];
__device__ __align__(16) float g_kft_re[128 * LF * 64];
__device__ __align__(16) float g_kft_im[128 * LF * 64];
// v spectra: [row=bh*64+e][y], padded pitch 514
__device__ __align__(16) float g_vf_re[NROW * VPITCH];
__device__ __align__(16) float g_vf_im[NROW * VPITCH];
__device__ float  g_of_re[NROW * LF];
__device__ float  g_of_im[NROW * LF];
__device__ float2 g_tw[512];

// ---------------- packed f32x2 helpers ------------------------------------
__device__ __forceinline__ unsigned long long pk2(float lo, float hi) {
    unsigned long long r;
    asm("mov.b64 %0, {%1, %2};" : "=l"(r) : "f"(lo), "f"(hi));
    return r;
}
__device__ __forceinline__ void upk2(unsigned long long v, float& lo, float& hi) {
    asm("mov.b64 {%0, %1}, %2;" : "=f"(lo), "=f"(hi) : "l"(v));
}
__device__ __forceinline__ unsigned long long ffma2(unsigned long long a,
                                                    unsigned long long b,
                                                    unsigned long long c) {
    unsigned long long d;
    asm("fma.rn.f32x2 %0, %1, %2, %3;" : "=l"(d) : "l"(a), "l"(b), "l"(c));
    return d;
}
__device__ __forceinline__ unsigned long long neg2(unsigned long long a) {
    return a ^ 0x8000000080000000ULL;
}
__device__ __forceinline__ float sigmoidf_(float x) {
    return 1.0f / (1.0f + __expf(-x));
}
__device__ __forceinline__ int rowbase(int r) { return r * 66; }

// cp.async helpers
__device__ __forceinline__ void cp8(unsigned int dst, const void* src, int srcsize) {
    asm volatile("cp.async.ca.shared.global [%0], [%1], 8, %2;"
                 :: "r"(dst), "l"(src), "r"(srcsize));
}
__device__ __forceinline__ void cp16(unsigned int dst, const void* src, int srcsize) {
    asm volatile("cp.async.cg.shared.global [%0], [%1], 16, %2;"
                 :: "r"(dst), "l"(src), "r"(srcsize));
}
__device__ __forceinline__ void cp_commit() {
    asm volatile("cp.async.commit_group;");
}
template <int N>
__device__ __forceinline__ void cp_wait() {
    asm volatile("cp.async.wait_group %0;" :: "n"(N));
}

// ---------------- init: transpose W + twiddle table ------------------------
__global__ __launch_bounds__(256) void init_kernel(const float* __restrict__ W) {
    int idx = blockIdx.x * 256 + threadIdx.x;
    if (idx < 2 * 1536 * 512) {
        int r = idx % 1536, oc = idx / 1536;
        int half = oc >> 9, o = oc & 511;
        g_Wt[((size_t)half * 1536 + r) * 512 + o] = W[idx];
    }
    if (blockIdx.x == 0) {
        for (int j = threadIdx.x; j < 512; j += 256) {
            float s, c;
            sincosf(6.283185307179586f * (float)j * (1.0f / 1024.0f), &s, &c);
            g_tw[j] = make_float2(c, s);
        }
    }
}

// ---------------- Conv1d(512->1024,k=3,p=1)+GLU, cp.async double-buffered --
__global__ __launch_bounds__(256, 2) void conv_glu_kernel(
        const float* __restrict__ q, const float* __restrict__ bias) {
    extern __shared__ float csm[];
    float* sx = csm;              // 2 * 1056
    float* sw = csm + 2112;       // 2 * 6144

    int b   = blockIdx.x >> 4;
    int l0  = (blockIdx.x & 15) << 6;
    int oc0 = blockIdx.y << 6;
    int tid = threadIdx.x;
    int tx  = tid & 15, ty = tid >> 4;
    int lb  = ty << 2;

    unsigned int sxa = (unsigned int)__cvta_generic_to_shared(sx);
    unsigned int swa = (unsigned int)__cvta_generic_to_shared(sw);

    auto issue = [&](int chunk, int buf) {
        int ic0 = chunk << 4;
        for (int t = tid; t < 264; t += 256) {
            int li = t >> 2, seg = t & 3;
            int l = l0 - 1 + li;
            int valid = (unsigned)l < 1024u;
            const float* src = q + ((size_t)b * 1024 + (valid ? l : 0)) * 512
                               + ic0 + (seg << 2);
            cp16(sxa + (unsigned)((buf * 1056 + li * 16 + (seg << 2)) * 4),
                 src, valid ? 16 : 0);
        }
#pragma unroll
        for (int o = 0; o < 6; o++) {
            int t = tid + (o << 8);
            int half = t >= 768;
            int tt = t - (half ? 768 : 0);
            int r = tt >> 4, seg = tt & 15;
            const float* src = g_Wt + ((size_t)half * 1536 + ic0 * 3 + r) * 512
                               + oc0 + (seg << 2);
            cp16(swa + (unsigned)((buf * 6144 + half * 3072 + r * 64 + (seg << 2)) * 4),
                 src, 16);
        }
        cp_commit();
    };

    issue(0, 0);

    unsigned long long pa[4][2], pg[4][2];
#pragma unroll
    for (int i = 0; i < 4; i++)
#pragma unroll
        for (int c = 0; c < 2; c++) { pa[i][c] = 0ull; pg[i][c] = 0ull; }

    for (int ch = 0; ch < 32; ch++) {
        int buf = ch & 1;
        if (ch < 31) {
            issue(ch + 1, buf ^ 1);
            cp_wait<1>();
        } else {
            cp_wait<0>();
        }
        __syncthreads();

        const float* xb = sx + buf * 1056;
        const float* wb = sw + buf * 6144;
#pragma unroll
        for (int ic = 0; ic < 16; ic++) {
            float xs[6];
#pragma unroll
            for (int s = 0; s < 6; s++) xs[s] = xb[(lb + s) * 16 + ic];
            unsigned long long xd[6];
#pragma unroll
            for (int s = 0; s < 6; s++) xd[s] = pk2(xs[s], xs[s]);
            unsigned long long wva[2][3], wvg[2][3];
#pragma unroll
            for (int c = 0; c < 2; c++)
#pragma unroll
                for (int kw = 0; kw < 3; kw++) {
                    int a = (ic * 3 + kw) * 64 + ((tx + (c << 4)) << 1);
                    wva[c][kw] = *(const unsigned long long*)(wb + a);
                    wvg[c][kw] = *(const unsigned long long*)(wb + 3072 + a);
                }
#pragma unroll
            for (int i = 0; i < 4; i++)
#pragma unroll
                for (int c = 0; c < 2; c++)
#pragma unroll
                    for (int kw = 0; kw < 3; kw++) {
                        pa[i][c] = ffma2(xd[i + kw], wva[c][kw], pa[i][c]);
                        pg[i][c] = ffma2(xd[i + kw], wvg[c][kw], pg[i][c]);
                    }
        }
        __syncthreads();
    }

    float* st = csm;
#pragma unroll
    for (int c = 0; c < 2; c++) {
        int p = tx + (c << 4);
        float b0a = bias[oc0 + 2 * p],       b1a = bias[oc0 + 2 * p + 1];
        float b0g = bias[512 + oc0 + 2 * p], b1g = bias[512 + oc0 + 2 * p + 1];
#pragma unroll
        for (int i = 0; i < 4; i++) {
            float a0, a1, g0, g1;
            upk2(pa[i][c], a0, a1);
            upk2(pg[i][c], g0, g1);
            st[(2 * p) * 65 + lb + i]     = (a0 + b0a) * sigmoidf_(g0 + b0g);
            st[(2 * p + 1) * 65 + lb + i] = (a1 + b1a) * sigmoidf_(g1 + b1g);
        }
    }
    __syncthreads();
#pragma unroll
    for (int t = 0; t < 16; t++) {
        int idx = tid + (t << 8);
        int c2 = idx >> 6, li = idx & 63;
        g_q2t[((size_t)b * 512 + oc0 + c2) * 1024 + l0 + li] = st[c2 * 65 + li];
    }
}

// ---------------- 1024-pt radix-2 Stockham (DIF, natural order) ------------
__device__ __forceinline__ void fft1024_shared(float2* bufA, float2* bufB,
                                               float sgn, int tid) {
    float2* src = bufA;
    float2* dst = bufB;
    int m = 1;
#pragma unroll
    for (int stage = 0; stage < 10; stage++) {
#pragma unroll
        for (int u = 0; u < 2; u++) {
            int idx = tid + (u << 8);
            float2 c0 = src[idx];
            float2 c1 = src[idx + 512];
            int k = idx & (m - 1);
            int o = idx + (idx - k);
            float2 w = g_tw[idx - k];
            float wy = w.y * sgn;
            float trx = c0.x - c1.x, trY = c0.y - c1.y;
            dst[o]     = make_float2(c0.x + c1.x, c0.y + c1.y);
            dst[o + m] = make_float2(w.x * trx - wy * trY, w.x * trY + wy * trx);
        }
        __syncthreads();
        float2* t = src; src = dst; dst = t;
        m <<= 1;
    }
}

// all three rffts in one launch: blockIdx.y 0=q, 1=k, 2=v
__global__ __launch_bounds__(256) void rfft_all_kernel(const float* __restrict__ kin,
                                                       const float* __restrict__ vin) {
    __shared__ float2 bufA[1024];
    __shared__ float2 bufB[1024];
    int row = blockIdx.x, tid = threadIdx.x;
    int which = blockIdx.y;
    if (which == 0) {
        const float* p = g_q2t + (size_t)row * 1024;
        for (int i = tid; i < 1024; i += 256) bufA[i] = make_float2(p[i], 0.0f);
    } else {
        const float* in = (which == 2) ? vin : kin;
        const float* p = in + (size_t)(row >> 9) * 524288 + (row & 511);
        for (int i = tid; i < 1024; i += 256)
            bufA[i] = make_float2(p[(size_t)i * 512], 0.0f);
    }
    __syncthreads();
    fft1024_shared(bufA, bufB, -1.0f, tid);
    if (which == 2) {
        size_t ob = (size_t)row * VPITCH;
        for (int i = tid; i < 513; i += 256) {
            float2 vv = bufA[i];
            g_vf_re[ob + i] = vv.x * 0.03125f;
            g_vf_im[ob + i] = vv.y * 0.03125f;
        }
    } else {
        int bh = row >> 6, e = row & 63;
        size_t ob = (size_t)bh * LF * 64 + e;
        float* ore = which ? g_kft_re : g_qft_re;
        float* oim = which ? g_kft_im : g_qft_im;
        for (int i = tid; i < 513; i += 256) {
            float2 vv = bufA[i];
            ore[ob + (size_t)i * 64] = vv.x * 0.03125f;
            oim[ob + (size_t)i * 64] = vv.y * 0.03125f;
        }
    }
}

// ---------------- fused frequency attention: 32-x tile, occ-2 --------------
// smem floats: Q 2*2112, K 2*4224, V 2*4224, T 2*2112 = 25344 (101376 B)
__global__ __launch_bounds__(256, 2) void attn_kernel() {
    extern __shared__ float sm[];
    float* Qre = sm;                  // [32 x][64 e] pitch 66
    float* Qim = sm + 2112;
    float* Kre = sm + 4224;           // [64 y][64 e] pitch 66
    float* Kim = sm + 8448;
    float* Vre = sm + 12672;          // [64 e][64 y] pitch 66
    float* Vim = sm + 16896;
    float* Tre = sm + 21120;          // [32 x][64 y] pitch 66
    float* Tim = sm + 23232;

    int bh  = blockIdx.y;
    int x0  = blockIdx.x << 5;        // 17 tiles of 32
    int tid = threadIdx.x;
    int tx  = tid & 15, ty = tid >> 4;
    size_t tbase = (size_t)bh * LF * 64;
    size_t obase = (size_t)bh * 64 * LF;

    unsigned int sQre = (unsigned int)__cvta_generic_to_shared(Qre);
    unsigned int sQim = (unsigned int)__cvta_generic_to_shared(Qim);
    unsigned int sKre = (unsigned int)__cvta_generic_to_shared(Kre);
    unsigned int sKim = (unsigned int)__cvta_generic_to_shared(Kim);
    unsigned int sVre = (unsigned int)__cvta_generic_to_shared(Vre);
    unsigned int sVim = (unsigned int)__cvta_generic_to_shared(Vim);

    {
        // Q tile: 32 rows x 32 e-pairs
#pragma unroll
        for (int o = 0; o < 4; o++) {
            int flat = tid + (o << 8);
            int r = flat >> 5, p = flat & 31;
            int valid = (x0 + r) < 513;
            const float* sre = g_qft_re + tbase + (size_t)(x0 + r) * 64 + 2 * p;
            const float* sim = g_qft_im + tbase + (size_t)(x0 + r) * 64 + 2 * p;
            unsigned int d = (unsigned int)((r * 66 + 2 * p) * 4);
            cp8(sQre + d, valid ? sre : g_qft_re, valid ? 8 : 0);
            cp8(sQim + d, valid ? sim : g_qft_im, valid ? 8 : 0);
        }
        // K tile 0: 64 rows
#pragma unroll
        for (int o = 0; o < 8; o++) {
            int flat = tid + (o << 8);
            int r = flat >> 5, p = flat & 31;
            const float* sre = g_kft_re + tbase + (size_t)r * 64 + 2 * p;
            const float* sim = g_kft_im + tbase + (size_t)r * 64 + 2 * p;
            unsigned int d = (unsigned int)((r * 66 + 2 * p) * 4);
            cp8(sKre + d, sre, 8);
            cp8(sKim + d, sim, 8);
        }
        cp_commit();
        // V tile 0
#pragma unroll
        for (int o = 0; o < 8; o++) {
            int flat = tid + (o << 8);
            int r = flat >> 5, p = flat & 31;
            const float* sre = g_vf_re + (size_t)(bh * 64 + r) * VPITCH + 2 * p;
            const float* sim = g_vf_im + (size_t)(bh * 64 + r) * VPITCH + 2 * p;
            unsigned int d = (unsigned int)((r * 66 + 2 * p) * 4);
            cp8(sVre + d, sre, 8);
            cp8(sVim + d, sim, 8);
        }
        cp_commit();
    }

    int qb[2], kb[4];
#pragma unroll
    for (int i = 0; i < 2; i++) qb[i] = rowbase((ty << 1) + i);
#pragma unroll
    for (int j = 0; j < 4; j++) kb[j] = rowbase(tx + (j << 4));

    unsigned long long ore_p[2][4], oim_p[2][4];
#pragma unroll
    for (int i = 0; i < 2; i++)
#pragma unroll
        for (int j = 0; j < 4; j++) { ore_p[i][j] = 0ull; oim_p[i][j] = 0ull; }
    float Dacc[2] = {};

    cp_wait<1>();
    __syncthreads();

    for (int yt = 0; yt < 9; yt++) {
        unsigned long long sre_p[2][4], sim_p[2][4];
#pragma unroll
        for (int i = 0; i < 2; i++)
#pragma unroll
            for (int j = 0; j < 4; j++) { sre_p[i][j] = 0ull; sim_p[i][j] = 0ull; }

        for (int e2 = 0; e2 < 32; e2++) {
            unsigned long long qr[2], qi[2], qrn[2], kr[4], ki[4];
            int off = e2 << 1;
#pragma unroll
            for (int i = 0; i < 2; i++) {
                qr[i] = *(const unsigned long long*)(Qre + qb[i] + off);
                qi[i] = *(const unsigned long long*)(Qim + qb[i] + off);
                qrn[i] = neg2(qr[i]);
            }
#pragma unroll
            for (int j = 0; j < 4; j++) {
                kr[j] = *(const unsigned long long*)(Kre + kb[j] + off);
                ki[j] = *(const unsigned long long*)(Kim + kb[j] + off);
            }
#pragma unroll
            for (int i = 0; i < 2; i++)
#pragma unroll
                for (int j = 0; j < 4; j++) {
                    sre_p[i][j] = ffma2(qr[i],  kr[j], sre_p[i][j]);
                    sre_p[i][j] = ffma2(qi[i],  ki[j], sre_p[i][j]);
                    sim_p[i][j] = ffma2(qi[i],  kr[j], sim_p[i][j]);
                    sim_p[i][j] = ffma2(qrn[i], ki[j], sim_p[i][j]);
                }
        }
        __syncthreads();

        if (yt < 8) {
            int y0n = (yt + 1) << 6;
#pragma unroll
            for (int o = 0; o < 8; o++) {
                int flat = tid + (o << 8);
                int r = flat >> 5, p = flat & 31;
                int valid = (y0n + r) < 513;
                const float* sre = g_kft_re + tbase + (size_t)(y0n + r) * 64 + 2 * p;
                const float* sim = g_kft_im + tbase + (size_t)(y0n + r) * 64 + 2 * p;
                unsigned int d = (unsigned int)((r * 66 + 2 * p) * 4);
                cp8(sKre + d, valid ? sre : g_kft_re, valid ? 8 : 0);
                cp8(sKim + d, valid ? sim : g_kft_im, valid ? 8 : 0);
            }
            cp_commit();
        }

#pragma unroll
        for (int i = 0; i < 2; i++)
#pragma unroll
            for (int j = 0; j < 4; j++) {
                float a0, a1, b0, b1;
                upk2(sre_p[i][j], a0, a1);
                upk2(sim_p[i][j], b0, b1);
                float sr = (a0 + a1) * 0.125f;
                float si = (b0 + b1) * 0.125f;
                float mg = sqrtf(sr * sr + si * si);
                float w  = 1.0f + sigmoidf_(mg);
                Dacc[i] += mg * w;
                int a = qb[i] + tx + (j << 4);
                Tre[a] = sr * w;
                Tim[a] = si * w;
            }

        if (yt < 8) cp_wait<1>(); else cp_wait<0>();
        __syncthreads();

        for (int y2 = 0; y2 < 32; y2++) {
            unsigned long long tr[2], ti[2], tin[2], vr[4], vi[4];
            int off = y2 << 1;
#pragma unroll
            for (int i = 0; i < 2; i++) {
                tr[i] = *(const unsigned long long*)(Tre + qb[i] + off);
                ti[i] = *(const unsigned long long*)(Tim + qb[i] + off);
                tin[i] = neg2(ti[i]);
            }
#pragma unroll
            for (int j = 0; j < 4; j++) {
                vr[j] = *(const unsigned long long*)(Vre + kb[j] + off);
                vi[j] = *(const unsigned long long*)(Vim + kb[j] + off);
            }
#pragma unroll
            for (int i = 0; i < 2; i++)
#pragma unroll
                for (int j = 0; j < 4; j++) {
                    ore_p[i][j] = ffma2(tr[i],  vr[j], ore_p[i][j]);
                    ore_p[i][j] = ffma2(tin[i], vi[j], ore_p[i][j]);
                    oim_p[i][j] = ffma2(tr[i],  vi[j], oim_p[i][j]);
                    oim_p[i][j] = ffma2(ti[i],  vr[j], oim_p[i][j]);
                }
        }
        __syncthreads();

        if (yt < 8) {
            int y0n = (yt + 1) << 6;
#pragma unroll
            for (int o = 0; o < 8; o++) {
                int flat = tid + (o << 8);
                int r = flat >> 5, p = flat & 31;
                int rem = 513 - (y0n + 2 * p);
                int sz = rem >= 2 ? 8 : (rem == 1 ? 4 : 0);
                const float* sre = g_vf_re + (size_t)(bh * 64 + r) * VPITCH + y0n + 2 * p;
                const float* sim = g_vf_im + (size_t)(bh * 64 + r) * VPITCH + y0n + 2 * p;
                unsigned int d = (unsigned int)((r * 66 + 2 * p) * 4);
                cp8(sVre + d, sre, sz);
                cp8(sVim + d, sim, sz);
            }
            cp_commit();
            cp_wait<1>();
            __syncthreads();
        }
    }

#pragma unroll
    for (int i = 0; i < 2; i++) {
        float dsum = Dacc[i];
        dsum += __shfl_xor_sync(0xffffffffu, dsum, 1);
        dsum += __shfl_xor_sync(0xffffffffu, dsum, 2);
        dsum += __shfl_xor_sync(0xffffffffu, dsum, 4);
        dsum += __shfl_xor_sync(0xffffffffu, dsum, 8);
        Dacc[i] = 1.0f / fmaxf(dsum, 1e-12f);
    }
#pragma unroll
    for (int i = 0; i < 2; i++) {
        int x = x0 + (ty << 1) + i;
        if (x < 513) {
#pragma unroll
            for (int j = 0; j < 4; j++) {
                int e = tx + (j << 4);
                float a0, a1, b0, b1;
                upk2(ore_p[i][j], a0, a1);
                upk2(oim_p[i][j], b0, b1);
                g_of_re[obase + (size_t)e * 513 + x] = (a0 + a1) * Dacc[i];
                g_of_im[obase + (size_t)e * 513 + x] = (b0 + b1) * Dacc[i];
            }
        }
    }
}

// ---------------- irfft (ortho) + scatter to out[b,l,h,e] ------------------
__global__ __launch_bounds__(256) void irfft_kernel(float* __restrict__ out) {
    __shared__ float2 bufA[1024];
    __shared__ float2 bufB[1024];
    int row = blockIdx.x, tid = threadIdx.x;
    const float* pr = g_of_re + (size_t)row * 513;
    const float* pi = g_of_im + (size_t)row * 513;
    for (int i = tid; i < 1024; i += 256) {
        float re, im;
        if (i < 513) { re = pr[i];        im =  pi[i]; }
        else         { re = pr[1024 - i]; im = -pi[1024 - i]; }
        bufA[i] = make_float2(re, im);
    }
    __syncthreads();
    fft1024_shared(bufA, bufB, 1.0f, tid);
    int b = row >> 9, c = row & 511;
    float* po = out + (size_t)b * 524288 + c;
    for (int i = tid; i < 1024; i += 256)
        po[(size_t)i * 512] = bufA[i].x * 0.03125f;
}

// ---------------- launch ---------------------------------------------------
extern "C" void kernel_launch(void* const* d_in, const int* in_sizes, int n_in,
                              void* d_out, int out_size) {
    const float* q    = (const float*)d_in[0];
    const float* k    = (const float*)d_in[1];
    const float* v    = (const float*)d_in[2];
    const float* W    = (const float*)d_in[3];
    const float* bias = (const float*)d_in[4];
    float* out = (float*)d_out;

    const int attn_smem = 25344 * (int)sizeof(float);   // 101376 B
    cudaFuncSetAttribute(attn_kernel,
                         cudaFuncAttributeMaxDynamicSharedMemorySize, attn_smem);
    const int conv_smem = (2112 + 12288) * (int)sizeof(float);  // 57600 B
    cudaFuncSetAttribute(conv_glu_kernel,
                         cudaFuncAttributeMaxDynamicSharedMemorySize, conv_smem);

    init_kernel<<<6144, 256>>>(W);
    conv_glu_kernel<<<dim3(256, 8), 256, conv_smem>>>(q, bias);
    rfft_all_kernel<<<dim3(NROW, 3), 256>>>(k, v);
    attn_kernel<<<dim3(17, 128), 256, attn_smem>>>();   // ncu slot (4th)
    irfft_kernel<<<NROW, 256>>>(out);
}

// round 11
// speedup vs baseline: 1.8954x; 1.2186x over previous
#include <cuda_runtime.h>
#include <cuda_bf16.h>
#include <math.h>

#define B_   16
#define L_   1024
#define H_   8
#define E_   64
#define D_   512
#define LF   513
#define NROW 8192            // B_*D_
#define VPITCH 514

// ---------------- device scratch (no cudaMalloc allowed) -------------------
__device__ __align__(16) __nv_bfloat16 g_Abh[16384 * 1536];  // im2col hi
__device__ __align__(16) __nv_bfloat16 g_Abl[16384 * 1536];  // im2col lo
__device__ __align__(16) __nv_bfloat16 g_Wbh[1024 * 1536];   // W hi [oc][r]
__device__ __align__(16) __nv_bfloat16 g_Wbl[1024 * 1536];   // W lo
__device__ __align__(16) float g_conv[16384 * 1024];         // conv out (a|g)+bias
// transposed spectra: [bh][x][e], contiguous in e
__device__ __align__(16) float g_qft_re[128 * LF * 64];
__device__ __align__(16) float g_qft_im[128 * LF * 64];
__device__ __align__(16) float g_kft_re[128 * LF * 64];
__device__ __align__(16) float g_kft_im[128 * LF * 64];
// v spectra: [row=bh*64+e][y], padded pitch 514
__device__ __align__(16) float g_vf_re[NROW * VPITCH];
__device__ __align__(16) float g_vf_im[NROW * VPITCH];
__device__ float  g_of_re[NROW * LF];
__device__ float  g_of_im[NROW * LF];
__device__ float2 g_tw[512];

// ---------------- packed f32x2 helpers ------------------------------------
__device__ __forceinline__ unsigned long long pk2(float lo, float hi) {
    unsigned long long r;
    asm("mov.b64 %0, {%1, %2};" : "=l"(r) : "f"(lo), "f"(hi));
    return r;
}
__device__ __forceinline__ void upk2(unsigned long long v, float& lo, float& hi) {
    asm("mov.b64 {%0, %1}, %2;" : "=f"(lo), "=f"(hi) : "l"(v));
}
__device__ __forceinline__ unsigned long long ffma2(unsigned long long a,
                                                    unsigned long long b,
                                                    unsigned long long c) {
    unsigned long long d;
    asm("fma.rn.f32x2 %0, %1, %2, %3;" : "=l"(d) : "l"(a), "l"(b), "l"(c));
    return d;
}
__device__ __forceinline__ unsigned long long neg2(unsigned long long a) {
    return a ^ 0x8000000080000000ULL;
}
__device__ __forceinline__ float sigmoidf_(float x) {
    return 1.0f / (1.0f + __expf(-x));
}
__device__ __forceinline__ int rowbase(int r) { return r * 66; }

// cp.async helpers
__device__ __forceinline__ void cp8(unsigned int dst, const void* src, int srcsize) {
    asm volatile("cp.async.ca.shared.global [%0], [%1], 8, %2;"
                 :: "r"(dst), "l"(src), "r"(srcsize));
}
__device__ __forceinline__ void cp16(unsigned int dst, const void* src, int srcsize) {
    asm volatile("cp.async.cg.shared.global [%0], [%1], 16, %2;"
                 :: "r"(dst), "l"(src), "r"(srcsize));
}
__device__ __forceinline__ void cp_commit() {
    asm volatile("cp.async.commit_group;");
}
template <int N>
__device__ __forceinline__ void cp_wait() {
    asm volatile("cp.async.wait_group %0;" :: "n"(N));
}

// ---------------- mma.sync helpers (sm_80-path; compiles on compute_103) ---
__device__ __forceinline__ void ldmx4(unsigned* r, unsigned a) {
    asm volatile("ldmatrix.sync.aligned.m8n8.x4.shared.b16 {%0,%1,%2,%3}, [%4];"
                 : "=r"(r[0]), "=r"(r[1]), "=r"(r[2]), "=r"(r[3]) : "r"(a));
}
__device__ __forceinline__ void mma_bf16(float* c, const unsigned* a,
                                         const unsigned* b) {
    asm volatile(
        "mma.sync.aligned.m16n8k16.row.col.f32.bf16.bf16.f32 "
        "{%0,%1,%2,%3}, {%4,%5,%6,%7}, {%8,%9}, {%0,%1,%2,%3};"
        : "+f"(c[0]), "+f"(c[1]), "+f"(c[2]), "+f"(c[3])
        : "r"(a[0]), "r"(a[1]), "r"(a[2]), "r"(a[3]), "r"(b[0]), "r"(b[1]));
}

// ---------------- init: split W to bf16 hi/lo + twiddle table --------------
__global__ __launch_bounds__(256) void init_kernel(const float* __restrict__ W) {
    int idx = blockIdx.x * 256 + threadIdx.x;     // exactly 1024*1536
    float w = W[idx];
    __nv_bfloat16 h = __float2bfloat16(w);
    g_Wbh[idx] = h;
    g_Wbl[idx] = __float2bfloat16(w - __bfloat162float(h));
    if (blockIdx.x == 0) {
        for (int j = threadIdx.x; j < 512; j += 256) {
            float s, c;
            sincosf(6.283185307179586f * (float)j * (1.0f / 1024.0f), &s, &c);
            g_tw[j] = make_float2(c, s);
        }
    }
}

// ---------------- im2col + bf16 split: q -> A[16384][1536] hi/lo -----------
__global__ __launch_bounds__(256) void im2col_kernel(const float* __restrict__ q) {
    int idx = blockIdx.x * 256 + threadIdx.x;     // exactly 16384*1536
    int row = idx / 1536, r = idx - row * 1536;
    int ic = r / 3, kw = r - ic * 3;
    int b = row >> 10, l = row & 1023;
    int ls = l + kw - 1;
    float v = 0.0f;
    if ((unsigned)ls < 1024u) v = q[((size_t)b * 1024 + ls) * 512 + ic];
    __nv_bfloat16 h = __float2bfloat16(v);
    g_Abh[idx] = h;
    g_Abl[idx] = __float2bfloat16(v - __bfloat162float(h));
}

// ---------------- Conv GEMM via mma.sync bf16 split-3 ----------------------
// D[128 l, 64 oc] = sum_k A[l,k]*W[oc,k]; K=1536 in 48 chunks of 32.
// 8 warps: 4(m) x 2(n), warp tile 32x32, mma m16n8k16, 3 terms hi/lo.
// smem per buf: Ah 8K | Al 8K | Bh 4K | Bl 4K = 24576 B; double = 49152 B.
// Swizzle: 16B seg' = seg ^ ((row>>1)&3), row stride 64B.
__global__ __launch_bounds__(256, 2) void conv_mma_kernel(
        const float* __restrict__ bias) {
    extern __shared__ char csmc[];
    unsigned sbase = (unsigned)__cvta_generic_to_shared(csmc);
    int tid = threadIdx.x;
    int wid = tid >> 5, lane = tid & 31;
    int n0 = blockIdx.x << 6;     // 16 n tiles
    int m0 = blockIdx.y << 7;     // 128 m tiles
    int wm = wid >> 1, wn = wid & 1;

    auto issue = [&](int ch, int buf) {
        unsigned tb = sbase + (unsigned)buf * 24576u;
        int k0 = ch << 5;
        const __nv_bfloat16* Ah = g_Abh + (size_t)m0 * 1536 + k0;
        const __nv_bfloat16* Al = g_Abl + (size_t)m0 * 1536 + k0;
#pragma unroll
        for (int o = 0; o < 2; o++) {
            int idx = tid + (o << 8);            // < 512
            int row = idx >> 2, seg = idx & 3;
            unsigned dst = tb + (unsigned)(row * 64 + ((seg ^ ((row >> 1) & 3)) << 4));
            cp16(dst,         Ah + (size_t)row * 1536 + seg * 8, 16);
            cp16(dst + 8192u, Al + (size_t)row * 1536 + seg * 8, 16);
        }
        const __nv_bfloat16* Bh = g_Wbh + (size_t)n0 * 1536 + k0;
        const __nv_bfloat16* Bl = g_Wbl + (size_t)n0 * 1536 + k0;
        {
            int row = tid >> 2, seg = tid & 3;   // 256 = 64 rows x 4 segs
            unsigned dst = tb + 16384u
                + (unsigned)(row * 64 + ((seg ^ ((row >> 1) & 3)) << 4));
            cp16(dst,         Bh + (size_t)row * 1536 + seg * 8, 16);
            cp16(dst + 4096u, Bl + (size_t)row * 1536 + seg * 8, 16);
        }
        cp_commit();
    };

    float acc[2][4][4];
#pragma unroll
    for (int mt = 0; mt < 2; mt++)
#pragma unroll
        for (int nt = 0; nt < 4; nt++)
#pragma unroll
            for (int i = 0; i < 4; i++) acc[mt][nt][i] = 0.0f;

    issue(0, 0);

    for (int ch = 0; ch < 48; ch++) {
        int buf = ch & 1;
        if (ch < 47) { issue(ch + 1, buf ^ 1); cp_wait<1>(); }
        else         { cp_wait<0>(); }
        __syncthreads();
        unsigned tb = sbase + (unsigned)buf * 24576u;

#pragma unroll
        for (int s = 0; s < 2; s++) {
            unsigned ah[2][4], al[2][4];
#pragma unroll
            for (int mt = 0; mt < 2; mt++) {
                int row = (wm << 5) + (mt << 4) + (lane & 15);
                int seg = (s << 1) + (lane >> 4);
                unsigned a = tb + (unsigned)(row * 64 + ((seg ^ ((row >> 1) & 3)) << 4));
                ldmx4(ah[mt], a);
                ldmx4(al[mt], a + 8192u);
            }
            unsigned bh[4][2], bl[4][2];
#pragma unroll
            for (int np = 0; np < 2; np++) {
                int row = (wn << 5) + (np << 4) + ((lane >> 4) << 3) + (lane & 7);
                int seg = (s << 1) + ((lane >> 3) & 1);
                unsigned a = tb + 16384u
                    + (unsigned)(row * 64 + ((seg ^ ((row >> 1) & 3)) << 4));
                unsigned r[4];
                ldmx4(r, a);
                bh[np * 2][0] = r[0]; bh[np * 2][1] = r[1];
                bh[np * 2 + 1][0] = r[2]; bh[np * 2 + 1][1] = r[3];
                ldmx4(r, a + 4096u);
                bl[np * 2][0] = r[0]; bl[np * 2][1] = r[1];
                bl[np * 2 + 1][0] = r[2]; bl[np * 2 + 1][1] = r[3];
            }
#pragma unroll
            for (int mt = 0; mt < 2; mt++)
#pragma unroll
                for (int nt = 0; nt < 4; nt++) {
                    mma_bf16(acc[mt][nt], ah[mt], bh[nt]);
                    mma_bf16(acc[mt][nt], ah[mt], bl[nt]);
                    mma_bf16(acc[mt][nt], al[mt], bh[nt]);
                }
        }
        __syncthreads();
    }

    // epilogue: C frag (c0,c1)=(row, col..col+1), (c2,c3)=(row+8, ..)
    int r0 = m0 + (wm << 5) + (lane >> 2);
    int c0 = n0 + (wn << 5) + ((lane & 3) << 1);
#pragma unroll
    for (int mt = 0; mt < 2; mt++)
#pragma unroll
        for (int nt = 0; nt < 4; nt++) {
            int row = r0 + (mt << 4);
            int col = c0 + (nt << 3);
            float b0v = bias[col], b1v = bias[col + 1];
            *(float2*)(g_conv + (size_t)row * 1024 + col) =
                make_float2(acc[mt][nt][0] + b0v, acc[mt][nt][1] + b1v);
            *(float2*)(g_conv + (size_t)(row + 8) * 1024 + col) =
                make_float2(acc[mt][nt][2] + b0v, acc[mt][nt][3] + b1v);
        }
}

// ---------------- 1024-pt radix-2 Stockham (DIF, natural order) ------------
__device__ __forceinline__ void fft1024_shared(float2* bufA, float2* bufB,
                                               float sgn, int tid) {
    float2* src = bufA;
    float2* dst = bufB;
    int m = 1;
#pragma unroll
    for (int stage = 0; stage < 10; stage++) {
#pragma unroll
        for (int u = 0; u < 2; u++) {
            int idx = tid + (u << 8);
            float2 c0 = src[idx];
            float2 c1 = src[idx + 512];
            int k = idx & (m - 1);
            int o = idx + (idx - k);
            float2 w = g_tw[idx - k];
            float wy = w.y * sgn;
            float trx = c0.x - c1.x, trY = c0.y - c1.y;
            dst[o]     = make_float2(c0.x + c1.x, c0.y + c1.y);
            dst[o + m] = make_float2(w.x * trx - wy * trY, w.x * trY + wy * trx);
        }
        __syncthreads();
        float2* t = src; src = dst; dst = t;
        m <<= 1;
    }
}

// rffts of k (-> transposed) and v (-> padded rows): blockIdx.y 0=k, 1=v
__global__ __launch_bounds__(256) void rfft_kv_kernel(const float* __restrict__ kin,
                                                      const float* __restrict__ vin) {
    __shared__ float2 bufA[1024];
    __shared__ float2 bufB[1024];
    int row = blockIdx.x, tid = threadIdx.x;
    int isv = blockIdx.y;
    const float* in = isv ? vin : kin;
    const float* p = in + (size_t)(row >> 9) * 524288 + (row & 511);
    for (int i = tid; i < 1024; i += 256)
        bufA[i] = make_float2(p[(size_t)i * 512], 0.0f);
    __syncthreads();
    fft1024_shared(bufA, bufB, -1.0f, tid);
    if (isv) {
        size_t ob = (size_t)row * VPITCH;
        for (int i = tid; i < 513; i += 256) {
            float2 vv = bufA[i];
            g_vf_re[ob + i] = vv.x * 0.03125f;
            g_vf_im[ob + i] = vv.y * 0.03125f;
        }
    } else {
        int bh = row >> 6, e = row & 63;
        size_t ob = (size_t)bh * LF * 64 + e;
        for (int i = tid; i < 513; i += 256) {
            float2 vv = bufA[i];
            g_kft_re[ob + (size_t)i * 64] = vv.x * 0.03125f;
            g_kft_im[ob + (size_t)i * 64] = vv.y * 0.03125f;
        }
    }
}

// rfft of q with fused GLU load: q2[l] = a[l]*sigmoid(g[l]) from g_conv
__global__ __launch_bounds__(256) void rfft_q_kernel() {
    __shared__ float2 bufA[1024];
    __shared__ float2 bufB[1024];
    int row = blockIdx.x, tid = threadIdx.x;   // row = b*512 + c
    int b = row >> 9, c = row & 511;
    const float* p = g_conv + (size_t)b * 1024 * 1024 + c;
    for (int i = tid; i < 1024; i += 256) {
        float a = p[(size_t)i * 1024];
        float g = p[(size_t)i * 1024 + 512];
        bufA[i] = make_float2(a * sigmoidf_(g), 0.0f);
    }
    __syncthreads();
    fft1024_shared(bufA, bufB, -1.0f, tid);
    int bh = row >> 6, e = row & 63;
    size_t ob = (size_t)bh * LF * 64 + e;
    for (int i = tid; i < 513; i += 256) {
        float2 vv = bufA[i];
        g_qft_re[ob + (size_t)i * 64] = vv.x * 0.03125f;
        g_qft_im[ob + (size_t)i * 64] = vv.y * 0.03125f;
    }
}

// ---------------- fused frequency attention: 32-x tile, occ-2 --------------
__global__ __launch_bounds__(256, 2) void attn_kernel() {
    extern __shared__ float sm[];
    float* Qre = sm;                  // [32 x][64 e] pitch 66
    float* Qim = sm + 2112;
    float* Kre = sm + 4224;           // [64 y][64 e] pitch 66
    float* Kim = sm + 8448;
    float* Vre = sm + 12672;          // [64 e][64 y] pitch 66
    float* Vim = sm + 16896;
    float* Tre = sm + 21120;          // [32 x][64 y] pitch 66
    float* Tim = sm + 23232;

    int bh  = blockIdx.y;
    int x0  = blockIdx.x << 5;
    int tid = threadIdx.x;
    int tx  = tid & 15, ty = tid >> 4;
    size_t tbase = (size_t)bh * LF * 64;
    size_t obase = (size_t)bh * 64 * LF;

    unsigned int sQre = (unsigned int)__cvta_generic_to_shared(Qre);
    unsigned int sQim = (unsigned int)__cvta_generic_to_shared(Qim);
    unsigned int sKre = (unsigned int)__cvta_generic_to_shared(Kre);
    unsigned int sKim = (unsigned int)__cvta_generic_to_shared(Kim);
    unsigned int sVre = (unsigned int)__cvta_generic_to_shared(Vre);
    unsigned int sVim = (unsigned int)__cvta_generic_to_shared(Vim);

    {
#pragma unroll
        for (int o = 0; o < 4; o++) {
            int flat = tid + (o << 8);
            int r = flat >> 5, p = flat & 31;
            int valid = (x0 + r) < 513;
            const float* sre = g_qft_re + tbase + (size_t)(x0 + r) * 64 + 2 * p;
            const float* sim = g_qft_im + tbase + (size_t)(x0 + r) * 64 + 2 * p;
            unsigned int d = (unsigned int)((r * 66 + 2 * p) * 4);
            cp8(sQre + d, valid ? sre : g_qft_re, valid ? 8 : 0);
            cp8(sQim + d, valid ? sim : g_qft_im, valid ? 8 : 0);
        }
#pragma unroll
        for (int o = 0; o < 8; o++) {
            int flat = tid + (o << 8);
            int r = flat >> 5, p = flat & 31;
            const float* sre = g_kft_re + tbase + (size_t)r * 64 + 2 * p;
            const float* sim = g_kft_im + tbase + (size_t)r * 64 + 2 * p;
            unsigned int d = (unsigned int)((r * 66 + 2 * p) * 4);
            cp8(sKre + d, sre, 8);
            cp8(sKim + d, sim, 8);
        }
        cp_commit();
#pragma unroll
        for (int o = 0; o < 8; o++) {
            int flat = tid + (o << 8);
            int r = flat >> 5, p = flat & 31;
            const float* sre = g_vf_re + (size_t)(bh * 64 + r) * VPITCH + 2 * p;
            const float* sim = g_vf_im + (size_t)(bh * 64 + r) * VPITCH + 2 * p;
            unsigned int d = (unsigned int)((r * 66 + 2 * p) * 4);
            cp8(sVre + d, sre, 8);
            cp8(sVim + d, sim, 8);
        }
        cp_commit();
    }

    int qb[2], kb[4];
#pragma unroll
    for (int i = 0; i < 2; i++) qb[i] = rowbase((ty << 1) + i);
#pragma unroll
    for (int j = 0; j < 4; j++) kb[j] = rowbase(tx + (j << 4));

    unsigned long long ore_p[2][4], oim_p[2][4];
#pragma unroll
    for (int i = 0; i < 2; i++)
#pragma unroll
        for (int j = 0; j < 4; j++) { ore_p[i][j] = 0ull; oim_p[i][j] = 0ull; }
    float Dacc[2] = {};

    cp_wait<1>();
    __syncthreads();

    for (int yt = 0; yt < 9; yt++) {
        unsigned long long sre_p[2][4], sim_p[2][4];
#pragma unroll
        for (int i = 0; i < 2; i++)
#pragma unroll
            for (int j = 0; j < 4; j++) { sre_p[i][j] = 0ull; sim_p[i][j] = 0ull; }

        for (int e2 = 0; e2 < 32; e2++) {
            unsigned long long qr[2], qi[2], qrn[2], kr[4], ki[4];
            int off = e2 << 1;
#pragma unroll
            for (int i = 0; i < 2; i++) {
                qr[i] = *(const unsigned long long*)(Qre + qb[i] + off);
                qi[i] = *(const unsigned long long*)(Qim + qb[i] + off);
                qrn[i] = neg2(qr[i]);
            }
#pragma unroll
            for (int j = 0; j < 4; j++) {
                kr[j] = *(const unsigned long long*)(Kre + kb[j] + off);
                ki[j] = *(const unsigned long long*)(Kim + kb[j] + off);
            }
#pragma unroll
            for (int i = 0; i < 2; i++)
#pragma unroll
                for (int j = 0; j < 4; j++) {
                    sre_p[i][j] = ffma2(qr[i],  kr[j], sre_p[i][j]);
                    sre_p[i][j] = ffma2(qi[i],  ki[j], sre_p[i][j]);
                    sim_p[i][j] = ffma2(qi[i],  kr[j], sim_p[i][j]);
                    sim_p[i][j] = ffma2(qrn[i], ki[j], sim_p[i][j]);
                }
        }
        __syncthreads();

        if (yt < 8) {
            int y0n = (yt + 1) << 6;
#pragma unroll
            for (int o = 0; o < 8; o++) {
                int flat = tid + (o << 8);
                int r = flat >> 5, p = flat & 31;
                int valid = (y0n + r) < 513;
                const float* sre = g_kft_re + tbase + (size_t)(y0n + r) * 64 + 2 * p;
                const float* sim = g_kft_im + tbase + (size_t)(y0n + r) * 64 + 2 * p;
                unsigned int d = (unsigned int)((r * 66 + 2 * p) * 4);
                cp8(sKre + d, valid ? sre : g_kft_re, valid ? 8 : 0);
                cp8(sKim + d, valid ? sim : g_kft_im, valid ? 8 : 0);
            }
            cp_commit();
        }

#pragma unroll
        for (int i = 0; i < 2; i++)
#pragma unroll
            for (int j = 0; j < 4; j++) {
                float a0, a1, b0, b1;
                upk2(sre_p[i][j], a0, a1);
                upk2(sim_p[i][j], b0, b1);
                float sr = (a0 + a1) * 0.125f;
                float si = (b0 + b1) * 0.125f;
                float mg = sqrtf(sr * sr + si * si);
                float w  = 1.0f + sigmoidf_(mg);
                Dacc[i] += mg * w;
                int a = qb[i] + tx + (j << 4);
                Tre[a] = sr * w;
                Tim[a] = si * w;
            }

        if (yt < 8) cp_wait<1>(); else cp_wait<0>();
        __syncthreads();

        for (int y2 = 0; y2 < 32; y2++) {
            unsigned long long tr[2], ti[2], tin[2], vr[4], vi[4];
            int off = y2 << 1;
#pragma unroll
            for (int i = 0; i < 2; i++) {
                tr[i] = *(const unsigned long long*)(Tre + qb[i] + off);
                ti[i] = *(const unsigned long long*)(Tim + qb[i] + off);
                tin[i] = neg2(ti[i]);
            }
#pragma unroll
            for (int j = 0; j < 4; j++) {
                vr[j] = *(const unsigned long long*)(Vre + kb[j] + off);
                vi[j] = *(const unsigned long long*)(Vim + kb[j] + off);
            }
#pragma unroll
            for (int i = 0; i < 2; i++)
#pragma unroll
                for (int j = 0; j < 4; j++) {
                    ore_p[i][j] = ffma2(tr[i],  vr[j], ore_p[i][j]);
                    ore_p[i][j] = ffma2(tin[i], vi[j], ore_p[i][j]);
                    oim_p[i][j] = ffma2(tr[i],  vi[j], oim_p[i][j]);
                    oim_p[i][j] = ffma2(ti[i],  vr[j], oim_p[i][j]);
                }
        }
        __syncthreads();

        if (yt < 8) {
            int y0n = (yt + 1) << 6;
#pragma unroll
            for (int o = 0; o < 8; o++) {
                int flat = tid + (o << 8);
                int r = flat >> 5, p = flat & 31;
                int rem = 513 - (y0n + 2 * p);
                int sz = rem >= 2 ? 8 : (rem == 1 ? 4 : 0);
                const float* sre = g_vf_re + (size_t)(bh * 64 + r) * VPITCH + y0n + 2 * p;
                const float* sim = g_vf_im + (size_t)(bh * 64 + r) * VPITCH + y0n + 2 * p;
                unsigned int d = (unsigned int)((r * 66 + 2 * p) * 4);
                cp8(sVre + d, sre, sz);
                cp8(sVim + d, sim, sz);
            }
            cp_commit();
            cp_wait<1>();
            __syncthreads();
        }
    }

#pragma unroll
    for (int i = 0; i < 2; i++) {
        float dsum = Dacc[i];
        dsum += __shfl_xor_sync(0xffffffffu, dsum, 1);
        dsum += __shfl_xor_sync(0xffffffffu, dsum, 2);
        dsum += __shfl_xor_sync(0xffffffffu, dsum, 4);
        dsum += __shfl_xor_sync(0xffffffffu, dsum, 8);
        Dacc[i] = 1.0f / fmaxf(dsum, 1e-12f);
    }
#pragma unroll
    for (int i = 0; i < 2; i++) {
        int x = x0 + (ty << 1) + i;
        if (x < 513) {
#pragma unroll
            for (int j = 0; j < 4; j++) {
                int e = tx + (j << 4);
                float a0, a1, b0, b1;
                upk2(ore_p[i][j], a0, a1);
                upk2(oim_p[i][j], b0, b1);
                g_of_re[obase + (size_t)e * 513 + x] = (a0 + a1) * Dacc[i];
                g_of_im[obase + (size_t)e * 513 + x] = (b0 + b1) * Dacc[i];
            }
        }
    }
}

// ---------------- irfft (ortho) + scatter to out[b,l,h,e] ------------------
__global__ __launch_bounds__(256) void irfft_kernel(float* __restrict__ out) {
    __shared__ float2 bufA[1024];
    __shared__ float2 bufB[1024];
    int row = blockIdx.x, tid = threadIdx.x;
    const float* pr = g_of_re + (size_t)row * 513;
    const float* pi = g_of_im + (size_t)row * 513;
    for (int i = tid; i < 1024; i += 256) {
        float re, im;
        if (i < 513) { re = pr[i];        im =  pi[i]; }
        else         { re = pr[1024 - i]; im = -pi[1024 - i]; }
        bufA[i] = make_float2(re, im);
    }
    __syncthreads();
    fft1024_shared(bufA, bufB, 1.0f, tid);
    int b = row >> 9, c = row & 511;
    float* po = out + (size_t)b * 524288 + c;
    for (int i = tid; i < 1024; i += 256)
        po[(size_t)i * 512] = bufA[i].x * 0.03125f;
}

// ---------------- launch ---------------------------------------------------
extern "C" void kernel_launch(void* const* d_in, const int* in_sizes, int n_in,
                              void* d_out, int out_size) {
    const float* q    = (const float*)d_in[0];
    const float* k    = (const float*)d_in[1];
    const float* v    = (const float*)d_in[2];
    const float* W    = (const float*)d_in[3];
    const float* bias = (const float*)d_in[4];
    float* out = (float*)d_out;

    const int attn_smem = 25344 * (int)sizeof(float);       // 101376 B
    cudaFuncSetAttribute(attn_kernel,
                         cudaFuncAttributeMaxDynamicSharedMemorySize, attn_smem);
    const int conv_smem = 49152;                            // 2 x 24576 B
    cudaFuncSetAttribute(conv_mma_kernel,
                         cudaFuncAttributeMaxDynamicSharedMemorySize, conv_smem);

    init_kernel<<<6144, 256>>>(W);                          // 1024*1536 / 256
    im2col_kernel<<<98304, 256>>>(q);                       // 16384*1536 / 256
    rfft_kv_kernel<<<dim3(NROW, 2), 256>>>(k, v);
    conv_mma_kernel<<<dim3(16, 128), 256, conv_smem>>>(bias);   // ncu slot (4th)
    rfft_q_kernel<<<NROW, 256>>>();
    attn_kernel<<<dim3(17, 128), 256, attn_smem>>>();
    irfft_kernel<<<NROW, 256>>>(out);
}